// round 8
// baseline (speedup 1.0000x reference)
#include <cuda_runtime.h>
#include <math.h>

#define BB   256
#define HH   512
#define DD   512
#define NS   64
#define G5   2560
#define GRID 148
#define TPB  512

// dynamic smem layout:
//   big phase: A-dup (ull) [2][16][130] at 0 (33280 B), B (float) [2][16][132] at 33280 (16896 B)
//   step phase: per half h at h*25600: A-dup [2][16][66] (16896 B), B [2][16][68] (8704 B)
#define DYN_BYTES 51200
#define BIGB_OFF  33280
#define STB_OFF   16896
#define HALF_OFF  25600

// ---------------- packed fp32 helpers (sm_100+ base feature) ----------------
__device__ __forceinline__ unsigned long long dup2(float a) {
    unsigned long long d;
    asm("mov.b64 %0, {%1, %1};" : "=l"(d) : "f"(a));
    return d;
}
__device__ __forceinline__ void ffma2(unsigned long long& acc, unsigned long long a, unsigned long long b) {
    asm("fma.rn.f32x2 %0, %1, %2, %0;" : "+l"(acc) : "l"(a), "l"(b));
}
__device__ __forceinline__ float2 unpk(unsigned long long v) {
    float2 r;
    asm("mov.b64 {%0, %1}, %2;" : "=f"(r.x), "=f"(r.y) : "l"(v));
    return r;
}

// ---------------- static device scratch ----------------
__device__ float g_h [BB * NS * HH];
__device__ float g_c [BB * NS * HH];
__device__ float g_ch[BB * NS * HH];
__device__ float g_cc[BB * NS * HH];
__device__ float g_vl[(size_t)BB * NS * G5];
__device__ float g_vr[(size_t)BB * NS * G5];
__device__ float g_clog[BB * NS];
__device__ int   g_seq [BB * 32];
__device__ int4  g_jobs[BB * 2];
__device__ int   g_active[BB];
__device__ int   g_nact[32];
__device__ int   g_rowmap[BB * 32];
__device__ int   g_nrow;
__device__ int   g_bar_cnt = 0;
__device__ volatile int g_bar_gen = 0;

__device__ __forceinline__ float sigf(float x) { return 1.f / (1.f + expf(-x)); }

// ---------------- software grid barrier ----------------
__device__ __forceinline__ void gbar(int tid, int* gen)
{
    __syncthreads();
    if (tid == 0) {
        int target = *gen + 1;
        __threadfence();
        if (atomicAdd(&g_bar_cnt, 1) == GRID - 1) {
            g_bar_cnt = 0;
            __threadfence();
            g_bar_gen = target;
        } else {
            while (g_bar_gen - target < 0) __nanosleep(32);
            __threadfence();   // gpu-scope fence: drop stale L1 lines
        }
        *gen = target;
    }
    __syncthreads();
}

// ---------------- big GEMM tile: 128x128, BK=16, 512 threads, f32x2 ----------------
// mode 0: word proj   A = x[rowmap], B = W_word, +b_word -> g_h/g_c
// mode 1: leaf xform  A = g_h[rowmap slots], B = [Wl;Wr]  -> g_vl/g_vr
#define BIGA(buf,k,r) Ad[((buf)*16 + (k))*130 + (r)]
#define BIGB(buf,k,r) Bf[((buf)*16 + (k))*132 + (r)]
__device__ void gemm_big(int mode, int m0, int n0, int NROW, int tid,
    char* dynp, int* __restrict__ srow,
    const float* __restrict__ x, const float* __restrict__ Ww,
    const float* __restrict__ bw, const float* __restrict__ Wc)
{
    unsigned long long* Ad = (unsigned long long*)dynp;
    float* Bf = (float*)(dynp + BIGB_OFF);

    __syncthreads();
    if (tid < 128) {
        int r = m0 + tid;
        srow[tid] = (r < NROW) ? g_rowmap[r] : g_rowmap[0];
    }
    __syncthreads();

    const int lrow = tid >> 2;        // 0..127
    const int kq   = (tid & 3) * 4;   // 0,4,8,12

    const float* aptr;
    {
        int m = srow[lrow];
        aptr = (mode == 0) ? x + (size_t)m * DD + kq
                           : g_h + (size_t)(((m >> 5) << 6) + (m & 31)) * HH + kq;
    }
    const float* bptr;
    {
        int n = n0 + lrow;
        if (mode == 0) bptr = Ww + (size_t)n * DD + kq;
        else bptr = (n < G5) ? Wc + (size_t)n * 1024 + kq
                             : Wc + (size_t)(n - G5) * 1024 + 512 + kq;
    }

    const int ty = tid >> 5;   // warp id 0..15 -> rows ty*8 (smem broadcast)
    const int tx = tid & 31;   // lane -> cols tx*4 (2 packed pairs)

    unsigned long long acc[8][2];
#pragma unroll
    for (int i = 0; i < 8; i++) { acc[i][0] = 0ull; acc[i][1] = 0ull; }

    float4 ra = *reinterpret_cast<const float4*>(aptr);
    float4 rb = *reinterpret_cast<const float4*>(bptr);
    BIGA(0, kq + 0, lrow) = dup2(ra.x); BIGA(0, kq + 1, lrow) = dup2(ra.y);
    BIGA(0, kq + 2, lrow) = dup2(ra.z); BIGA(0, kq + 3, lrow) = dup2(ra.w);
    BIGB(0, kq + 0, lrow) = rb.x; BIGB(0, kq + 1, lrow) = rb.y;
    BIGB(0, kq + 2, lrow) = rb.z; BIGB(0, kq + 3, lrow) = rb.w;
    __syncthreads();

    int buf = 0;
    for (int k0 = 16; k0 <= 512; k0 += 16) {
        const bool more = (k0 < 512);
        if (more) {
            ra = *reinterpret_cast<const float4*>(aptr + k0);
            rb = *reinterpret_cast<const float4*>(bptr + k0);
        }
#pragma unroll
        for (int kk = 0; kk < 16; kk++) {
            unsigned long long a[8], b[2];
            const ulonglong2* ap = reinterpret_cast<const ulonglong2*>(&BIGA(buf, kk, ty * 8));
            *reinterpret_cast<ulonglong2*>(a)     = ap[0];
            *reinterpret_cast<ulonglong2*>(a + 2) = ap[1];
            *reinterpret_cast<ulonglong2*>(a + 4) = ap[2];
            *reinterpret_cast<ulonglong2*>(a + 6) = ap[3];
            *reinterpret_cast<ulonglong2*>(b)     = *reinterpret_cast<const ulonglong2*>(&BIGB(buf, kk, tx * 4));
#pragma unroll
            for (int i = 0; i < 8; i++) {
                ffma2(acc[i][0], a[i], b[0]);
                ffma2(acc[i][1], a[i], b[1]);
            }
        }
        if (more) {
            BIGA(buf ^ 1, kq + 0, lrow) = dup2(ra.x); BIGA(buf ^ 1, kq + 1, lrow) = dup2(ra.y);
            BIGA(buf ^ 1, kq + 2, lrow) = dup2(ra.z); BIGA(buf ^ 1, kq + 3, lrow) = dup2(ra.w);
            BIGB(buf ^ 1, kq + 0, lrow) = rb.x; BIGB(buf ^ 1, kq + 1, lrow) = rb.y;
            BIGB(buf ^ 1, kq + 2, lrow) = rb.z; BIGB(buf ^ 1, kq + 3, lrow) = rb.w;
        }
        __syncthreads();
        buf ^= 1;
    }

    const int nb = n0 + tx * 4;
    if (mode == 0) {
        float4 bi = *reinterpret_cast<const float4*>(&bw[nb]);
#pragma unroll
        for (int i = 0; i < 8; i++) {
            int r = ty * 8 + i;
            if (m0 + r < NROW) {
                int m = srow[r];
                int slot = ((m >> 5) << 6) + (m & 31);
                float* dst = (nb < HH) ? (g_h + (size_t)slot * HH + nb)
                                       : (g_c + (size_t)slot * HH + (nb - HH));
                float2 p0 = unpk(acc[i][0]), p1 = unpk(acc[i][1]);
                *reinterpret_cast<float4*>(dst) =
                    make_float4(p0.x + bi.x, p0.y + bi.y, p1.x + bi.z, p1.y + bi.w);
            }
        }
    } else {
#pragma unroll
        for (int i = 0; i < 8; i++) {
            int r = ty * 8 + i;
            if (m0 + r < NROW) {
                int m = srow[r];
                int slot = ((m >> 5) << 6) + (m & 31);
                size_t base = (size_t)slot * G5;
                float* dst = (nb < G5) ? (g_vl + base + nb) : (g_vr + base + (nb - G5));
                float2 p0 = unpk(acc[i][0]), p1 = unpk(acc[i][1]);
                *reinterpret_cast<float4*>(dst) = make_float4(p0.x, p0.y, p1.x, p1.y);
            }
        }
    }
}

// ---------------- step GEMM half-tile: 64x64, BK=16, 256 threads, f32x2 ----------------
// Both halves of the block MUST call this with identical trip counts (lockstep syncthreads).
#define STA(buf,k,r) Ad[((buf)*16 + (k))*66 + (r)]
#define STB(buf,k,r) Bf[((buf)*16 + (k))*68 + (r)]
__device__ void gemm_step(int step, int nact, int m0, int n0, bool tvalid, int t,
    char* hs, const float* __restrict__ Wc)
{
    unsigned long long* Ad = (unsigned long long*)hs;
    float* Bf = (float*)(hs + STB_OFF);

    const int lrow = t >> 2;        // 0..63
    const int kq   = (t & 3) * 4;

    const float* aptr;
    {
        int m = m0 + lrow;
        int b = (tvalid && m < nact) ? g_active[m] : 0;
        aptr = g_h + (size_t)(b * NS + 32 + step) * HH + kq;
    }
    const float* bptr;
    {
        int n = tvalid ? (n0 + lrow) : lrow;
        bptr = (n < G5) ? Wc + (size_t)n * 1024 + kq
                        : Wc + (size_t)(n - G5) * 1024 + 512 + kq;
    }

    const int ty = t >> 4;   // rows ty*4
    const int tx = t & 15;   // cols tx*4 (2 packed pairs)

    unsigned long long acc[4][2];
#pragma unroll
    for (int i = 0; i < 4; i++) { acc[i][0] = 0ull; acc[i][1] = 0ull; }

    float4 ra = *reinterpret_cast<const float4*>(aptr);
    float4 rb = *reinterpret_cast<const float4*>(bptr);
    STA(0, kq + 0, lrow) = dup2(ra.x); STA(0, kq + 1, lrow) = dup2(ra.y);
    STA(0, kq + 2, lrow) = dup2(ra.z); STA(0, kq + 3, lrow) = dup2(ra.w);
    STB(0, kq + 0, lrow) = rb.x; STB(0, kq + 1, lrow) = rb.y;
    STB(0, kq + 2, lrow) = rb.z; STB(0, kq + 3, lrow) = rb.w;
    __syncthreads();

    int buf = 0;
    for (int k0 = 16; k0 <= 512; k0 += 16) {
        const bool more = (k0 < 512);
        if (more) {
            ra = *reinterpret_cast<const float4*>(aptr + k0);
            rb = *reinterpret_cast<const float4*>(bptr + k0);
        }
#pragma unroll
        for (int kk = 0; kk < 16; kk++) {
            unsigned long long a[4], b[2];
            const ulonglong2* ap = reinterpret_cast<const ulonglong2*>(&STA(buf, kk, ty * 4));
            *reinterpret_cast<ulonglong2*>(a)     = ap[0];
            *reinterpret_cast<ulonglong2*>(a + 2) = ap[1];
            *reinterpret_cast<ulonglong2*>(b)     = *reinterpret_cast<const ulonglong2*>(&STB(buf, kk, tx * 4));
#pragma unroll
            for (int i = 0; i < 4; i++) {
                ffma2(acc[i][0], a[i], b[0]);
                ffma2(acc[i][1], a[i], b[1]);
            }
        }
        if (more) {
            STA(buf ^ 1, kq + 0, lrow) = dup2(ra.x); STA(buf ^ 1, kq + 1, lrow) = dup2(ra.y);
            STA(buf ^ 1, kq + 2, lrow) = dup2(ra.z); STA(buf ^ 1, kq + 3, lrow) = dup2(ra.w);
            STB(buf ^ 1, kq + 0, lrow) = rb.x; STB(buf ^ 1, kq + 1, lrow) = rb.y;
            STB(buf ^ 1, kq + 2, lrow) = rb.z; STB(buf ^ 1, kq + 3, lrow) = rb.w;
        }
        __syncthreads();
        buf ^= 1;
    }

    if (tvalid) {
        const int nb = n0 + tx * 4;
#pragma unroll
        for (int i = 0; i < 4; i++) {
            int m = m0 + ty * 4 + i;
            if (m < nact) {
                int b = g_active[m];
                size_t base = (size_t)(b * NS + 32 + step) * G5;
                float* dst = (nb < G5) ? (g_vl + base + nb) : (g_vr + base + (nb - G5));
                float2 p0 = unpk(acc[i][0]), p1 = unpk(acc[i][1]);
                *reinterpret_cast<float4*>(dst) = make_float4(p0.x, p0.y, p1.x, p1.y);
            }
        }
    }
}

// ---------------- pair gates + partial logit (t in 0..127) ----------------
__device__ __forceinline__ float pair_body(int b, int key, int Ls, int Rs, int t,
    const float* __restrict__ b_comp, const float* __restrict__ cq)
{
    const float4* vl  = reinterpret_cast<const float4*>(g_vl + (size_t)(b * NS + Ls) * G5);
    const float4* vr  = reinterpret_cast<const float4*>(g_vr + (size_t)(b * NS + Rs) * G5);
    const float4* bc  = reinterpret_cast<const float4*>(b_comp);
    const float4* cl4 = reinterpret_cast<const float4*>(g_c + (size_t)(b * NS + Ls) * HH);
    const float4* cr4 = reinterpret_cast<const float4*>(g_c + (size_t)(b * NS + Rs) * HH);
    const float4* q4  = reinterpret_cast<const float4*>(cq);

    float vi[4], vfl[4], vfr[4], vu[4], vo[4];
    {
        float* dsts[5] = {vi, vfl, vfr, vu, vo};
#pragma unroll
        for (int g = 0; g < 5; g++) {
            float4 a = vl[g * 128 + t], bb = vr[g * 128 + t], c = bc[g * 128 + t];
            dsts[g][0] = a.x + bb.x + c.x; dsts[g][1] = a.y + bb.y + c.y;
            dsts[g][2] = a.z + bb.z + c.z; dsts[g][3] = a.w + bb.w + c.w;
        }
    }
    float4 cl = cl4[t], cr = cr4[t], qv = q4[t];
    float clv[4] = {cl.x, cl.y, cl.z, cl.w};
    float crv[4] = {cr.x, cr.y, cr.z, cr.w};
    float qa[4]  = {qv.x, qv.y, qv.z, qv.w};
    float hh[4], cc[4], part = 0.f;
#pragma unroll
    for (int e = 0; e < 4; e++) {
        float c = clv[e] * sigf(vfl[e] + 1.f) + crv[e] * sigf(vfr[e] + 1.f)
                + tanhf(vu[e]) * sigf(vi[e]);
        float h = sigf(vo[e]) * tanhf(c);
        cc[e] = c; hh[e] = h;
        part = fmaf(qa[e], h, part);
    }
    reinterpret_cast<float4*>(g_ch + (size_t)(b * NS + key) * HH)[t] = make_float4(hh[0], hh[1], hh[2], hh[3]);
    reinterpret_cast<float4*>(g_cc + (size_t)(b * NS + key) * HH)[t] = make_float4(cc[0], cc[1], cc[2], cc[3]);
    return part;
}

// ---------------- plan for batch b at step i (one warp) ----------------
__device__ __forceinline__ void plan_do(int b, int i, int lane, const int* __restrict__ length)
{
    int ell = length[b];
    if (i + 1 < ell) {
        int npairs = 31 - i;
        int seqv = g_seq[b * 32 + lane];
        bool valid = (lane < ell - i - 1);
        float lg = valid ? g_clog[b * NS + seqv] : -1e9f;
        float mx = lg;
#pragma unroll
        for (int o = 16; o; o >>= 1) mx = fmaxf(mx, __shfl_xor_sync(0xffffffffu, mx, o));
        unsigned bal = __ballot_sync(0xffffffffu, lg == mx);
        int k = __ffs(bal) - 1;   // first-max = jnp.argmax

        int s    = 32 + i;
        int sk   = __shfl_sync(0xffffffffu, seqv, k);
        int skm1 = __shfl_sync(0xffffffffu, seqv, (k > 0) ? (k - 1) : 0);
        int skp2 = __shfl_sync(0xffffffffu, seqv, (k + 2 < 32) ? (k + 2) : 31);

        const float4* sh = reinterpret_cast<const float4*>(g_ch + (size_t)(b * NS + sk) * HH);
        const float4* sc = reinterpret_cast<const float4*>(g_cc + (size_t)(b * NS + sk) * HH);
        float4* dh = reinterpret_cast<float4*>(g_h + (size_t)(b * NS + s) * HH);
        float4* dc = reinterpret_cast<float4*>(g_c + (size_t)(b * NS + s) * HH);
#pragma unroll
        for (int r = 0; r < 4; r++) {
            dh[lane + 32 * r] = sh[lane + 32 * r];
            dc[lane + 32 * r] = sc[lane + 32 * r];
        }
        if (lane == 0) {
            int idx = atomicAdd(&g_nact[i], 1);
            g_active[idx] = b;
            g_jobs[b * 2]     = make_int4(skm1, skm1, s, (k >= 1) ? 1 : 0);
            g_jobs[b * 2 + 1] = make_int4(s, s, skp2, (k <= npairs - 2) ? 1 : 0);
        }
        int nxt = __shfl_down_sync(0xffffffffu, seqv, 1);
        g_seq[b * 32 + lane] = (lane < k) ? seqv : ((lane == k) ? s : nxt);
    } else if (lane == 0) {
        g_jobs[b * 2]     = make_int4(0, 0, 0, 0);
        g_jobs[b * 2 + 1] = make_int4(0, 0, 0, 0);
    }
}

// ---------------- the persistent kernel ----------------
__global__ __launch_bounds__(TPB, 1) void persist_k(
    const float* __restrict__ x, const int* __restrict__ length,
    const float* __restrict__ W_word, const float* __restrict__ b_word,
    const float* __restrict__ W_comp, const float* __restrict__ b_comp,
    const float* __restrict__ cq, float* __restrict__ out)
{
    extern __shared__ __align__(16) char dynp[];
    __shared__ int   srow[128];
    __shared__ float sws[16];

    const int tid  = threadIdx.x;
    const int bid  = blockIdx.x;
    const int half = tid >> 8;     // 0/1
    const int t256 = tid & 255;
    int gen = 0;
    if (tid == 0) gen = g_bar_gen;

    // ---- init: rowmap (block 0), seq (block 1), nact (block 2) ----
    if (bid == 0) {
        int* slen = (int*)dynp;
        if (tid < BB) slen[tid] = length[tid];
        __syncthreads();
        if (tid < BB) {
            int s = 0;
            for (int q = 0; q < tid; q++) s += slen[q];
            int l = slen[tid];
            for (int k = 0; k < l; k++) g_rowmap[s + k] = tid * 32 + k;
            if (tid == BB - 1) g_nrow = s + l;
        }
    }
    if (bid == 1) {
        for (int idx = tid; idx < BB * 32; idx += TPB) g_seq[idx] = idx & 31;
    }
    if (bid == 2 && tid < 32) g_nact[tid] = 0;
    gbar(tid, &gen);

    const int NROW = g_nrow;
    const int MG   = (NROW + 127) >> 7;

    // ---- phase A: word projection over live rows ----
    for (int tt = bid; tt < MG * 8; tt += GRID)
        gemm_big(0, (tt >> 3) * 128, (tt & 7) * 128, NROW, tid, dynp, srow, x, W_word, b_word, W_comp);
    gbar(tid, &gen);

    // ---- phase B: leaf transforms over live rows ----
    for (int tt = bid; tt < MG * 40; tt += GRID)
        gemm_big(1, (tt / 40) * 128, (tt % 40) * 128, NROW, tid, dynp, srow, x, W_word, b_word, W_comp);
    gbar(tid, &gen);

    // ---- phase C: initial candidates (only pairs inside valid prefix) ----
    {
        const int grp = tid >> 7, t2 = tid & 127, w4 = (tid >> 5) & 3;
        for (int p = bid; p < 1984; p += GRID) {
            int j  = p * 4 + grp;
            int b  = j / 31;
            int jj = j - b * 31;
            bool valid = (jj + 1 < length[b]);
            float part = valid ? pair_body(b, jj, jj, jj + 1, t2, b_comp, cq) : 0.f;
#pragma unroll
            for (int o = 16; o; o >>= 1) part += __shfl_xor_sync(0xffffffffu, part, o);
            if ((t2 & 31) == 0) sws[grp * 4 + w4] = part;
            __syncthreads();
            if (t2 == 0 && valid)
                g_clog[b * NS + jj] = (sws[grp*4] + sws[grp*4+1] + sws[grp*4+2] + sws[grp*4+3])
                                      * 0.044194173824159216f;
            __syncthreads();
        }
    }
    gbar(tid, &gen);

    // ---- plan(0): batch b on block b/2 (warp 0 of each half) ----
    {
        int b = bid * 2 + half;
        if (b < BB && t256 < 32) plan_do(b, 0, tid & 31, length);
    }
    gbar(tid, &gen);

    // ---- main loop ----
    for (int i = 0; i < 30; i++) {
        // step GEMM: dual 64x64 tiles per block (lockstep halves)
        {
            int nact  = g_nact[i];
            int ntile = ((nact + 63) >> 6) * 80;
            char* hs = dynp + half * HALF_OFF;
            for (int tb = bid * 2; tb < ntile; tb += 2 * GRID) {
                int w = tb + half;
                bool tv = (w < ntile);
                int mgi = tv ? (w / 80) : 0;
                int ni  = tv ? (w % 80) : 0;
                gemm_step(i, nact, mgi * 64, ni * 64, tv, t256, hs, W_comp);
            }
        }
        gbar(tid, &gen);

        // PP: pair jobs of step i + plan(i+1), batch b on block b/2
        {
            int b = bid * 2 + half;
            bool bact = (b < BB);
            const int grp = tid >> 7, t2 = tid & 127, w4 = (tid >> 5) & 3;
            int4 job = make_int4(0, 0, 0, 0);
            if (bact) job = g_jobs[b * 2 + (t256 >> 7)];
            bool jact = bact && job.w;
            float part = jact ? pair_body(b, job.x, job.y, job.z, t2, b_comp, cq) : 0.f;
#pragma unroll
            for (int o = 16; o; o >>= 1) part += __shfl_xor_sync(0xffffffffu, part, o);
            if ((t2 & 31) == 0) sws[grp * 4 + w4] = part;
            __syncthreads();
            if (t2 == 0 && jact)
                g_clog[b * NS + job.x] = (sws[grp*4] + sws[grp*4+1] + sws[grp*4+2] + sws[grp*4+3])
                                         * 0.044194173824159216f;
            __syncthreads();
            if (bact && t256 < 32) plan_do(b, i + 1, tid & 31, length);
        }
        gbar(tid, &gen);
    }

    // ---- output: h of root slot ----
    {
        int b = bid * 2 + half;
        if (b < BB && t256 < 128) {
            int s = g_seq[b * 32];
            const float4* src = reinterpret_cast<const float4*>(g_h + (size_t)(b * NS + s) * HH);
            reinterpret_cast<float4*>(out)[b * 128 + t256] = src[t256];
        }
    }
}

// ---------------- launch ----------------
extern "C" void kernel_launch(void* const* d_in, const int* in_sizes, int n_in,
                              void* d_out, int out_size)
{
    const float* x      = (const float*)d_in[0];
    const int*   length = (const int*)  d_in[1];
    const float* W_word = (const float*)d_in[2];
    const float* b_word = (const float*)d_in[3];
    const float* W_comp = (const float*)d_in[4];
    const float* b_comp = (const float*)d_in[5];
    const float* cq     = (const float*)d_in[6];
    float* out = (float*)d_out;

    cudaFuncSetAttribute(persist_k, cudaFuncAttributeMaxDynamicSharedMemorySize, DYN_BYTES);
    persist_k<<<GRID, TPB, DYN_BYTES>>>(x, length, W_word, b_word, W_comp, b_comp, cq, out);
}

// round 9
// speedup vs baseline: 1.3939x; 1.3939x over previous
#include <cuda_runtime.h>
#include <math.h>

#define BB   256
#define HH   512
#define DD   512
#define NS   64
#define G5   2560
#define GRID 148
#define TPB  512

// dynamic smem:
//  big phase: A float [2][16][132] at 0 (16896 B), B float [2][16][132] at 16896
//  step phase: per half h at h*17408: A [2][16][68] (8704 B), B [2][16][68]
#define DYN_BYTES 36864
#define BIGB_OFF  16896
#define STB_OFF   8704
#define HALF_OFF  17408

typedef unsigned long long ull;

// ---------------- packed fp32 helpers ----------------
__device__ __forceinline__ ull dup2(float a) {
    ull d;
    asm("mov.b64 %0, {%1, %1};" : "=l"(d) : "f"(a));
    return d;
}
__device__ __forceinline__ void ffma2(ull& acc, ull a, ull b) {
    asm("fma.rn.f32x2 %0, %1, %2, %0;" : "+l"(acc) : "l"(a), "l"(b));
}
__device__ __forceinline__ float2 unpk(ull v) {
    float2 r;
    asm("mov.b64 {%0, %1}, %2;" : "=f"(r.x), "=f"(r.y) : "l"(v));
    return r;
}
#define HBAR(h) asm volatile("bar.sync %0, 256;" :: "r"((h) + 1) : "memory")

// ---------------- static device scratch ----------------
__device__ float g_h [BB * NS * HH];
__device__ float g_c [BB * NS * HH];
__device__ float g_ch[BB * NS * HH];
__device__ float g_cc[BB * NS * HH];
__device__ float g_vl[(size_t)BB * NS * G5];
__device__ float g_vr[(size_t)BB * NS * G5];
__device__ float g_clog[BB * NS];
__device__ int   g_seq [BB * 32];
__device__ int4  g_jobs[BB * 2];
__device__ int   g_active[BB];
__device__ int   g_nact[32];
__device__ int   g_rowmap[BB * 32];
__device__ int   g_nrow;
__device__ int   g_bar_cnt = 0;
__device__ volatile int g_bar_gen = 0;

__device__ __forceinline__ float sigf(float x) { return 1.f / (1.f + expf(-x)); }

// ---------------- software grid barrier ----------------
__device__ __forceinline__ void gbar(int tid, int* gen)
{
    __syncthreads();
    if (tid == 0) {
        int target = *gen + 1;
        __threadfence();
        if (atomicAdd(&g_bar_cnt, 1) == GRID - 1) {
            g_bar_cnt = 0;
            __threadfence();
            g_bar_gen = target;
        } else {
            while (g_bar_gen - target < 0) __nanosleep(32);
            __threadfence();   // gpu-scope fence: drop stale L1 lines
        }
        *gen = target;
    }
    __syncthreads();
}

// ---------------- big GEMM tile: 128x128, BK=16, 512 threads, packed-B f32x2 ----
// mode 0: word proj   A = x[rowmap], B = W_word, +b_word -> g_h/g_c
// mode 1: leaf xform  A = g_h[rowmap slots], B = [Wl;Wr]  -> g_vl/g_vr
#define BIGA(buf,k,r) Af[((buf)*16 + (k))*132 + (r)]
#define BIGB(buf,k,r) Bf[((buf)*16 + (k))*132 + (r)]
__device__ void gemm_big(int mode, int m0, int n0, int NROW, int tid,
    char* dynp, int* __restrict__ srow,
    const float* __restrict__ x, const float* __restrict__ Ww,
    const float* __restrict__ bw, const float* __restrict__ Wc)
{
    float* Af = (float*)dynp;
    float* Bf = (float*)(dynp + BIGB_OFF);

    __syncthreads();
    if (tid < 128) {
        int r = m0 + tid;
        srow[tid] = (r < NROW) ? g_rowmap[r] : g_rowmap[0];
    }
    __syncthreads();

    const int lrow = tid >> 2;        // 0..127
    const int kq   = (tid & 3) * 4;   // 0,4,8,12

    const float* aptr;
    {
        int m = srow[lrow];
        aptr = (mode == 0) ? x + (size_t)m * DD + kq
                           : g_h + (size_t)(((m >> 5) << 6) + (m & 31)) * HH + kq;
    }
    const float* bptr;
    {
        int n = n0 + lrow;
        if (mode == 0) bptr = Ww + (size_t)n * DD + kq;
        else bptr = (n < G5) ? Wc + (size_t)n * 1024 + kq
                             : Wc + (size_t)(n - G5) * 1024 + 512 + kq;
    }

    const int ty = tid >> 5;   // warp id 0..15 -> rows ty*8 (smem broadcast)
    const int tx = tid & 31;   // lane -> cols tx*4 (2 packed pairs)

    ull acc[8][2];
#pragma unroll
    for (int i = 0; i < 8; i++) { acc[i][0] = 0ull; acc[i][1] = 0ull; }

    float4 ra = *reinterpret_cast<const float4*>(aptr);
    float4 rb = *reinterpret_cast<const float4*>(bptr);
    BIGA(0, kq + 0, lrow) = ra.x; BIGA(0, kq + 1, lrow) = ra.y;
    BIGA(0, kq + 2, lrow) = ra.z; BIGA(0, kq + 3, lrow) = ra.w;
    BIGB(0, kq + 0, lrow) = rb.x; BIGB(0, kq + 1, lrow) = rb.y;
    BIGB(0, kq + 2, lrow) = rb.z; BIGB(0, kq + 3, lrow) = rb.w;
    __syncthreads();

    int buf = 0;
    for (int k0 = 16; k0 <= 512; k0 += 16) {
        const bool more = (k0 < 512);
        if (more) {
            ra = *reinterpret_cast<const float4*>(aptr + k0);
            rb = *reinterpret_cast<const float4*>(bptr + k0);
        }
#pragma unroll
        for (int kk = 0; kk < 16; kk++) {
            float4 a0 = *reinterpret_cast<const float4*>(&BIGA(buf, kk, ty * 8));
            float4 a1 = *reinterpret_cast<const float4*>(&BIGA(buf, kk, ty * 8 + 4));
            ull b[2];
            *reinterpret_cast<ulonglong2*>(b) =
                *reinterpret_cast<const ulonglong2*>(&BIGB(buf, kk, tx * 4));
            ull ad[8];
            ad[0] = dup2(a0.x); ad[1] = dup2(a0.y); ad[2] = dup2(a0.z); ad[3] = dup2(a0.w);
            ad[4] = dup2(a1.x); ad[5] = dup2(a1.y); ad[6] = dup2(a1.z); ad[7] = dup2(a1.w);
#pragma unroll
            for (int i = 0; i < 8; i++) {
                ffma2(acc[i][0], ad[i], b[0]);
                ffma2(acc[i][1], ad[i], b[1]);
            }
        }
        if (more) {
            BIGA(buf ^ 1, kq + 0, lrow) = ra.x; BIGA(buf ^ 1, kq + 1, lrow) = ra.y;
            BIGA(buf ^ 1, kq + 2, lrow) = ra.z; BIGA(buf ^ 1, kq + 3, lrow) = ra.w;
            BIGB(buf ^ 1, kq + 0, lrow) = rb.x; BIGB(buf ^ 1, kq + 1, lrow) = rb.y;
            BIGB(buf ^ 1, kq + 2, lrow) = rb.z; BIGB(buf ^ 1, kq + 3, lrow) = rb.w;
        }
        __syncthreads();
        buf ^= 1;
    }

    const int nb = n0 + tx * 4;
    if (mode == 0) {
        float4 bi = *reinterpret_cast<const float4*>(&bw[nb]);
#pragma unroll
        for (int i = 0; i < 8; i++) {
            int r = ty * 8 + i;
            if (m0 + r < NROW) {
                int m = srow[r];
                int slot = ((m >> 5) << 6) + (m & 31);
                float* dst = (nb < HH) ? (g_h + (size_t)slot * HH + nb)
                                       : (g_c + (size_t)slot * HH + (nb - HH));
                float2 p0 = unpk(acc[i][0]), p1 = unpk(acc[i][1]);
                *reinterpret_cast<float4*>(dst) =
                    make_float4(p0.x + bi.x, p0.y + bi.y, p1.x + bi.z, p1.y + bi.w);
            }
        }
    } else {
#pragma unroll
        for (int i = 0; i < 8; i++) {
            int r = ty * 8 + i;
            if (m0 + r < NROW) {
                int m = srow[r];
                int slot = ((m >> 5) << 6) + (m & 31);
                size_t base = (size_t)slot * G5;
                float* dst = (nb < G5) ? (g_vl + base + nb) : (g_vr + base + (nb - G5));
                float2 p0 = unpk(acc[i][0]), p1 = unpk(acc[i][1]);
                *reinterpret_cast<float4*>(dst) = make_float4(p0.x, p0.y, p1.x, p1.y);
            }
        }
    }
}

// ---------------- step GEMM half-tile: 64x64, BK=16, 256 threads, packed-B f32x2 ----
// Halves are INDEPENDENT: per-half named barrier, separate smem region.
#define STA(buf,k,r) Af[((buf)*16 + (k))*68 + (r)]
#define STB(buf,k,r) Bf[((buf)*16 + (k))*68 + (r)]
__device__ void gemm_step(int step, int nact, int m0, int n0, int t, int half,
    char* hs, const float* __restrict__ Wc)
{
    float* Af = (float*)hs;
    float* Bf = (float*)(hs + STB_OFF);

    const int lrow = t >> 2;        // 0..63
    const int kq   = (t & 3) * 4;

    const float* aptr;
    {
        int m = m0 + lrow;
        int b = (m < nact) ? g_active[m] : g_active[0];
        aptr = g_h + (size_t)(b * NS + 32 + step) * HH + kq;
    }
    const float* bptr;
    {
        int n = n0 + lrow;
        bptr = (n < G5) ? Wc + (size_t)n * 1024 + kq
                        : Wc + (size_t)(n - G5) * 1024 + 512 + kq;
    }

    const int ty = t >> 4;   // rows ty*4
    const int tx = t & 15;   // cols tx*4 (2 packed pairs)

    ull acc[4][2];
#pragma unroll
    for (int i = 0; i < 4; i++) { acc[i][0] = 0ull; acc[i][1] = 0ull; }

    float4 ra = *reinterpret_cast<const float4*>(aptr);
    float4 rb = *reinterpret_cast<const float4*>(bptr);
    STA(0, kq + 0, lrow) = ra.x; STA(0, kq + 1, lrow) = ra.y;
    STA(0, kq + 2, lrow) = ra.z; STA(0, kq + 3, lrow) = ra.w;
    STB(0, kq + 0, lrow) = rb.x; STB(0, kq + 1, lrow) = rb.y;
    STB(0, kq + 2, lrow) = rb.z; STB(0, kq + 3, lrow) = rb.w;
    HBAR(half);

    int buf = 0;
    for (int k0 = 16; k0 <= 512; k0 += 16) {
        const bool more = (k0 < 512);
        if (more) {
            ra = *reinterpret_cast<const float4*>(aptr + k0);
            rb = *reinterpret_cast<const float4*>(bptr + k0);
        }
#pragma unroll
        for (int kk = 0; kk < 16; kk++) {
            float4 a0 = *reinterpret_cast<const float4*>(&STA(buf, kk, ty * 4));
            ull b[2];
            *reinterpret_cast<ulonglong2*>(b) =
                *reinterpret_cast<const ulonglong2*>(&STB(buf, kk, tx * 4));
            ull ad[4];
            ad[0] = dup2(a0.x); ad[1] = dup2(a0.y); ad[2] = dup2(a0.z); ad[3] = dup2(a0.w);
#pragma unroll
            for (int i = 0; i < 4; i++) {
                ffma2(acc[i][0], ad[i], b[0]);
                ffma2(acc[i][1], ad[i], b[1]);
            }
        }
        if (more) {
            STA(buf ^ 1, kq + 0, lrow) = ra.x; STA(buf ^ 1, kq + 1, lrow) = ra.y;
            STA(buf ^ 1, kq + 2, lrow) = ra.z; STA(buf ^ 1, kq + 3, lrow) = ra.w;
            STB(buf ^ 1, kq + 0, lrow) = rb.x; STB(buf ^ 1, kq + 1, lrow) = rb.y;
            STB(buf ^ 1, kq + 2, lrow) = rb.z; STB(buf ^ 1, kq + 3, lrow) = rb.w;
        }
        HBAR(half);
        buf ^= 1;
    }

    const int nb = n0 + tx * 4;
#pragma unroll
    for (int i = 0; i < 4; i++) {
        int m = m0 + ty * 4 + i;
        if (m < nact) {
            int b = g_active[m];
            size_t base = (size_t)(b * NS + 32 + step) * G5;
            float* dst = (nb < G5) ? (g_vl + base + nb) : (g_vr + base + (nb - G5));
            float2 p0 = unpk(acc[i][0]), p1 = unpk(acc[i][1]);
            *reinterpret_cast<float4*>(dst) = make_float4(p0.x, p0.y, p1.x, p1.y);
        }
    }
    HBAR(half);   // protect smem reuse across consecutive tiles in this half
}

// ---------------- pair gates + partial logit (t in 0..127) ----------------
__device__ __forceinline__ float pair_body(int b, int key, int Ls, int Rs, int t,
    const float* __restrict__ b_comp, const float* __restrict__ cq)
{
    const float4* vl  = reinterpret_cast<const float4*>(g_vl + (size_t)(b * NS + Ls) * G5);
    const float4* vr  = reinterpret_cast<const float4*>(g_vr + (size_t)(b * NS + Rs) * G5);
    const float4* bc  = reinterpret_cast<const float4*>(b_comp);
    const float4* cl4 = reinterpret_cast<const float4*>(g_c + (size_t)(b * NS + Ls) * HH);
    const float4* cr4 = reinterpret_cast<const float4*>(g_c + (size_t)(b * NS + Rs) * HH);
    const float4* q4  = reinterpret_cast<const float4*>(cq);

    float vi[4], vfl[4], vfr[4], vu[4], vo[4];
    {
        float* dsts[5] = {vi, vfl, vfr, vu, vo};
#pragma unroll
        for (int g = 0; g < 5; g++) {
            float4 a = vl[g * 128 + t], bb = vr[g * 128 + t], c = bc[g * 128 + t];
            dsts[g][0] = a.x + bb.x + c.x; dsts[g][1] = a.y + bb.y + c.y;
            dsts[g][2] = a.z + bb.z + c.z; dsts[g][3] = a.w + bb.w + c.w;
        }
    }
    float4 cl = cl4[t], cr = cr4[t], qv = q4[t];
    float clv[4] = {cl.x, cl.y, cl.z, cl.w};
    float crv[4] = {cr.x, cr.y, cr.z, cr.w};
    float qa[4]  = {qv.x, qv.y, qv.z, qv.w};
    float hh[4], cc[4], part = 0.f;
#pragma unroll
    for (int e = 0; e < 4; e++) {
        float c = clv[e] * sigf(vfl[e] + 1.f) + crv[e] * sigf(vfr[e] + 1.f)
                + tanhf(vu[e]) * sigf(vi[e]);
        float h = sigf(vo[e]) * tanhf(c);
        cc[e] = c; hh[e] = h;
        part = fmaf(qa[e], h, part);
    }
    reinterpret_cast<float4*>(g_ch + (size_t)(b * NS + key) * HH)[t] = make_float4(hh[0], hh[1], hh[2], hh[3]);
    reinterpret_cast<float4*>(g_cc + (size_t)(b * NS + key) * HH)[t] = make_float4(cc[0], cc[1], cc[2], cc[3]);
    return part;
}

// ---------------- plan for batch b at step i (one warp) ----------------
__device__ __forceinline__ void plan_do(int b, int i, int lane, const int* __restrict__ length)
{
    int ell = length[b];
    if (i + 1 < ell) {
        int npairs = 31 - i;
        int seqv = g_seq[b * 32 + lane];
        bool valid = (lane < ell - i - 1);
        float lg = valid ? g_clog[b * NS + seqv] : -1e9f;
        float mx = lg;
#pragma unroll
        for (int o = 16; o; o >>= 1) mx = fmaxf(mx, __shfl_xor_sync(0xffffffffu, mx, o));
        unsigned bal = __ballot_sync(0xffffffffu, lg == mx);
        int k = __ffs(bal) - 1;   // first-max = jnp.argmax

        int s    = 32 + i;
        int sk   = __shfl_sync(0xffffffffu, seqv, k);
        int skm1 = __shfl_sync(0xffffffffu, seqv, (k > 0) ? (k - 1) : 0);
        int skp2 = __shfl_sync(0xffffffffu, seqv, (k + 2 < 32) ? (k + 2) : 31);

        const float4* sh = reinterpret_cast<const float4*>(g_ch + (size_t)(b * NS + sk) * HH);
        const float4* sc = reinterpret_cast<const float4*>(g_cc + (size_t)(b * NS + sk) * HH);
        float4* dh = reinterpret_cast<float4*>(g_h + (size_t)(b * NS + s) * HH);
        float4* dc = reinterpret_cast<float4*>(g_c + (size_t)(b * NS + s) * HH);
#pragma unroll
        for (int r = 0; r < 4; r++) {
            dh[lane + 32 * r] = sh[lane + 32 * r];
            dc[lane + 32 * r] = sc[lane + 32 * r];
        }
        if (lane == 0) {
            int idx = atomicAdd(&g_nact[i], 1);
            g_active[idx] = b;
            g_jobs[b * 2]     = make_int4(skm1, skm1, s, (k >= 1) ? 1 : 0);
            g_jobs[b * 2 + 1] = make_int4(s, s, skp2, (k <= npairs - 2) ? 1 : 0);
        }
        int nxt = __shfl_down_sync(0xffffffffu, seqv, 1);
        g_seq[b * 32 + lane] = (lane < k) ? seqv : ((lane == k) ? s : nxt);
    } else if (lane == 0) {
        g_jobs[b * 2]     = make_int4(0, 0, 0, 0);
        g_jobs[b * 2 + 1] = make_int4(0, 0, 0, 0);
    }
}

// ---------------- the persistent kernel ----------------
__global__ __launch_bounds__(TPB, 1) void persist_k(
    const float* __restrict__ x, const int* __restrict__ length,
    const float* __restrict__ W_word, const float* __restrict__ b_word,
    const float* __restrict__ W_comp, const float* __restrict__ b_comp,
    const float* __restrict__ cq, float* __restrict__ out)
{
    extern __shared__ __align__(16) char dynp[];
    __shared__ int   srow[128];
    __shared__ float sws[16];

    const int tid  = threadIdx.x;
    const int bid  = blockIdx.x;
    const int half = tid >> 8;     // 0/1
    const int t256 = tid & 255;
    int gen = 0;
    if (tid == 0) gen = g_bar_gen;

    // ---- init: rowmap (block 0), seq (block 1), nact (block 2) ----
    if (bid == 0) {
        int* slen = (int*)dynp;
        if (tid < BB) slen[tid] = length[tid];
        __syncthreads();
        if (tid < BB) {
            int s = 0;
            for (int q = 0; q < tid; q++) s += slen[q];
            int l = slen[tid];
            for (int k = 0; k < l; k++) g_rowmap[s + k] = tid * 32 + k;
            if (tid == BB - 1) g_nrow = s + l;
        }
    }
    if (bid == 1) {
        for (int idx = tid; idx < BB * 32; idx += TPB) g_seq[idx] = idx & 31;
    }
    if (bid == 2 && tid < 32) g_nact[tid] = 0;
    gbar(tid, &gen);

    const int NROW = g_nrow;
    const int MG   = (NROW + 127) >> 7;

    // ---- phase A: word projection over live rows ----
    for (int tt = bid; tt < MG * 8; tt += GRID)
        gemm_big(0, (tt >> 3) * 128, (tt & 7) * 128, NROW, tid, dynp, srow, x, W_word, b_word, W_comp);
    gbar(tid, &gen);

    // ---- phase B: leaf transforms over live rows ----
    for (int tt = bid; tt < MG * 40; tt += GRID)
        gemm_big(1, (tt / 40) * 128, (tt % 40) * 128, NROW, tid, dynp, srow, x, W_word, b_word, W_comp);
    gbar(tid, &gen);

    // ---- phase C: initial candidates (only pairs inside valid prefix) ----
    {
        const int grp = tid >> 7, t2 = tid & 127, w4 = (tid >> 5) & 3;
        for (int p = bid; p < 1984; p += GRID) {
            int j  = p * 4 + grp;
            int b  = j / 31;
            int jj = j - b * 31;
            bool valid = (jj + 1 < length[b]);
            float part = valid ? pair_body(b, jj, jj, jj + 1, t2, b_comp, cq) : 0.f;
#pragma unroll
            for (int o = 16; o; o >>= 1) part += __shfl_xor_sync(0xffffffffu, part, o);
            if ((t2 & 31) == 0) sws[grp * 4 + w4] = part;
            __syncthreads();
            if (t2 == 0 && valid)
                g_clog[b * NS + jj] = (sws[grp*4] + sws[grp*4+1] + sws[grp*4+2] + sws[grp*4+3])
                                      * 0.044194173824159216f;
            __syncthreads();
        }
    }
    gbar(tid, &gen);

    // ---- plan(0): batch b on block b/2 (warp 0 of each half) ----
    {
        int b = bid * 2 + half;
        if (b < BB && t256 < 32) plan_do(b, 0, tid & 31, length);
    }
    gbar(tid, &gen);

    // ---- main loop ----
    for (int i = 0; i < 30; i++) {
        // step GEMM: independent 64x64 half-tiles, spread across SMs first
        {
            int nact  = g_nact[i];
            int ntile = ((nact + 63) >> 6) * 80;
            char* hs = dynp + half * HALF_OFF;
            for (int w = half * GRID + bid; w < ntile; w += 2 * GRID)
                gemm_step(i, nact, (w / 80) * 64, (w % 80) * 64, t256, half, hs, W_comp);
        }
        gbar(tid, &gen);

        // PP: pair jobs of step i + plan(i+1), batch b on block b/2
        {
            int b = bid * 2 + half;
            bool bact = (b < BB);
            const int grp = tid >> 7, t2 = tid & 127, w4 = (tid >> 5) & 3;
            int4 job = make_int4(0, 0, 0, 0);
            if (bact) job = g_jobs[b * 2 + (t256 >> 7)];
            bool jact = bact && job.w;
            float part = jact ? pair_body(b, job.x, job.y, job.z, t2, b_comp, cq) : 0.f;
#pragma unroll
            for (int o = 16; o; o >>= 1) part += __shfl_xor_sync(0xffffffffu, part, o);
            if ((t2 & 31) == 0) sws[grp * 4 + w4] = part;
            __syncthreads();
            if (t2 == 0 && jact)
                g_clog[b * NS + job.x] = (sws[grp*4] + sws[grp*4+1] + sws[grp*4+2] + sws[grp*4+3])
                                         * 0.044194173824159216f;
            __syncthreads();
            if (bact && t256 < 32) plan_do(b, i + 1, tid & 31, length);
        }
        gbar(tid, &gen);
    }

    // ---- output: h of root slot ----
    {
        int b = bid * 2 + half;
        if (b < BB && t256 < 128) {
            int s = g_seq[b * 32];
            const float4* src = reinterpret_cast<const float4*>(g_h + (size_t)(b * NS + s) * HH);
            reinterpret_cast<float4*>(out)[b * 128 + t256] = src[t256];
        }
    }
}

// ---------------- launch ----------------
extern "C" void kernel_launch(void* const* d_in, const int* in_sizes, int n_in,
                              void* d_out, int out_size)
{
    const float* x      = (const float*)d_in[0];
    const int*   length = (const int*)  d_in[1];
    const float* W_word = (const float*)d_in[2];
    const float* b_word = (const float*)d_in[3];
    const float* W_comp = (const float*)d_in[4];
    const float* b_comp = (const float*)d_in[5];
    const float* cq     = (const float*)d_in[6];
    float* out = (float*)d_out;

    cudaFuncSetAttribute(persist_k, cudaFuncAttributeMaxDynamicSharedMemorySize, DYN_BYTES);
    persist_k<<<GRID, TPB, DYN_BYTES>>>(x, length, W_word, b_word, W_comp, b_comp, cq, out);
}

// round 10
// speedup vs baseline: 1.4173x; 1.0168x over previous
#include <cuda_runtime.h>
#include <math.h>

#define BB   256
#define HH   512
#define DD   512
#define NS   64
#define G5   2560
#define GRID 148
#define TPB  512

// dynamic smem:
//  big phase: A float [2][16][132] at 0 (16896 B), B float [2][16][132] at 16896
//  step phase: per half h at h*17408: A [2][16][68] (8704 B), B [2][16][68]
#define DYN_BYTES 36864
#define BIGB_OFF  16896
#define STB_OFF   8704
#define HALF_OFF  17408

typedef unsigned long long ull;

// ---------------- packed fp32 helpers ----------------
__device__ __forceinline__ ull dup2(float a) {
    ull d;
    asm("mov.b64 %0, {%1, %1};" : "=l"(d) : "f"(a));
    return d;
}
__device__ __forceinline__ void ffma2(ull& acc, ull a, ull b) {
    asm("fma.rn.f32x2 %0, %1, %2, %0;" : "+l"(acc) : "l"(a), "l"(b));
}
__device__ __forceinline__ float2 unpk(ull v) {
    float2 r;
    asm("mov.b64 {%0, %1}, %2;" : "=f"(r.x), "=f"(r.y) : "l"(v));
    return r;
}
#define HBAR(h) asm volatile("bar.sync %0, 256;" :: "r"((h) + 1) : "memory")

// ---------------- static device scratch ----------------
__device__ float g_h [BB * NS * HH];
__device__ float g_c [BB * NS * HH];
__device__ float g_ch[BB * NS * HH];
__device__ float g_cc[BB * NS * HH];
__device__ float g_vl[(size_t)BB * NS * G5];
__device__ float g_vr[(size_t)BB * NS * G5];
__device__ float g_clog[BB * NS];
__device__ int   g_seq [BB * 32];
__device__ int4  g_jobs[BB * 2];
__device__ int   g_active[BB];
__device__ int   g_nact[32];
__device__ int   g_rowmap[BB * 32];
__device__ int   g_nrow;
__device__ int   g_bar_cnt = 0;
__device__ volatile int g_bar_gen = 0;

__device__ __forceinline__ float sigf(float x) { return 1.f / (1.f + expf(-x)); }

// ---------------- software grid barrier ----------------
__device__ __forceinline__ void gbar(int tid, int* gen)
{
    __syncthreads();
    if (tid == 0) {
        int target = *gen + 1;
        __threadfence();
        if (atomicAdd(&g_bar_cnt, 1) == GRID - 1) {
            g_bar_cnt = 0;
            __threadfence();
            g_bar_gen = target;
        } else {
            while (g_bar_gen - target < 0) __nanosleep(32);
            __threadfence();   // gpu-scope fence: drop stale L1 lines
        }
        *gen = target;
    }
    __syncthreads();
}

// ---------------- big GEMM tile: 128x128, BK=16, 512 threads, M-packed f32x2 ----
// Thread computes 8 rows (4 packed pairs) x 4 cols.
// mode 0: word proj   A = x[rowmap], B = W_word, +b_word -> g_h/g_c
// mode 1: leaf xform  A = g_h[rowmap slots], B = [Wl;Wr]  -> g_vl/g_vr
#define BIGA(buf,k,r) Af[((buf)*16 + (k))*132 + (r)]
#define BIGB(buf,k,r) Bf[((buf)*16 + (k))*132 + (r)]
__device__ void gemm_big(int mode, int m0, int n0, int NROW, int tid,
    char* dynp, int* __restrict__ srow,
    const float* __restrict__ x, const float* __restrict__ Ww,
    const float* __restrict__ bw, const float* __restrict__ Wc)
{
    float* Af = (float*)dynp;
    float* Bf = (float*)(dynp + BIGB_OFF);

    __syncthreads();
    if (tid < 128) {
        int r = m0 + tid;
        srow[tid] = (r < NROW) ? g_rowmap[r] : g_rowmap[0];
    }
    __syncthreads();

    const int lrow = tid >> 2;        // 0..127
    const int kq   = (tid & 3) * 4;   // 0,4,8,12

    const float* aptr;
    {
        int m = srow[lrow];
        aptr = (mode == 0) ? x + (size_t)m * DD + kq
                           : g_h + (size_t)(((m >> 5) << 6) + (m & 31)) * HH + kq;
    }
    const float* bptr;
    {
        int n = n0 + lrow;
        if (mode == 0) bptr = Ww + (size_t)n * DD + kq;
        else bptr = (n < G5) ? Wc + (size_t)n * 1024 + kq
                             : Wc + (size_t)(n - G5) * 1024 + 512 + kq;
    }

    const int ty = tid >> 5;   // warp id 0..15 -> rows ty*8 (smem broadcast)
    const int tx = tid & 31;   // lane -> cols tx*4

    ull acc[4][4];   // [row-pair][col]
#pragma unroll
    for (int i = 0; i < 4; i++)
#pragma unroll
        for (int j = 0; j < 4; j++) acc[i][j] = 0ull;

    float4 ra = *reinterpret_cast<const float4*>(aptr);
    float4 rb = *reinterpret_cast<const float4*>(bptr);
    BIGA(0, kq + 0, lrow) = ra.x; BIGA(0, kq + 1, lrow) = ra.y;
    BIGA(0, kq + 2, lrow) = ra.z; BIGA(0, kq + 3, lrow) = ra.w;
    BIGB(0, kq + 0, lrow) = rb.x; BIGB(0, kq + 1, lrow) = rb.y;
    BIGB(0, kq + 2, lrow) = rb.z; BIGB(0, kq + 3, lrow) = rb.w;
    __syncthreads();

    int buf = 0;
    for (int k0 = 16; k0 <= 512; k0 += 16) {
        const bool more = (k0 < 512);
        if (more) {
            ra = *reinterpret_cast<const float4*>(aptr + k0);
            rb = *reinterpret_cast<const float4*>(bptr + k0);
        }
#pragma unroll
        for (int kk = 0; kk < 16; kk++) {
            ull a[4];   // 4 M-pairs, natural layout (adjacent rows contiguous)
            ulonglong2 t0 = *reinterpret_cast<const ulonglong2*>(&BIGA(buf, kk, ty * 8));
            ulonglong2 t1 = *reinterpret_cast<const ulonglong2*>(&BIGA(buf, kk, ty * 8 + 4));
            a[0] = t0.x; a[1] = t0.y; a[2] = t1.x; a[3] = t1.y;
            float4 b4 = *reinterpret_cast<const float4*>(&BIGB(buf, kk, tx * 4));
            ull bd[4];
            bd[0] = dup2(b4.x); bd[1] = dup2(b4.y); bd[2] = dup2(b4.z); bd[3] = dup2(b4.w);
#pragma unroll
            for (int i = 0; i < 4; i++)
#pragma unroll
                for (int j = 0; j < 4; j++)
                    ffma2(acc[i][j], a[i], bd[j]);
        }
        if (more) {
            BIGA(buf ^ 1, kq + 0, lrow) = ra.x; BIGA(buf ^ 1, kq + 1, lrow) = ra.y;
            BIGA(buf ^ 1, kq + 2, lrow) = ra.z; BIGA(buf ^ 1, kq + 3, lrow) = ra.w;
            BIGB(buf ^ 1, kq + 0, lrow) = rb.x; BIGB(buf ^ 1, kq + 1, lrow) = rb.y;
            BIGB(buf ^ 1, kq + 2, lrow) = rb.z; BIGB(buf ^ 1, kq + 3, lrow) = rb.w;
        }
        __syncthreads();
        buf ^= 1;
    }

    const int nb = n0 + tx * 4;
    float4 bi = make_float4(0.f, 0.f, 0.f, 0.f);
    if (mode == 0) bi = *reinterpret_cast<const float4*>(&bw[nb]);
#pragma unroll
    for (int p = 0; p < 4; p++) {
        float2 c0 = unpk(acc[p][0]), c1 = unpk(acc[p][1]);
        float2 c2 = unpk(acc[p][2]), c3 = unpk(acc[p][3]);
        float4 row0 = make_float4(c0.x + bi.x, c1.x + bi.y, c2.x + bi.z, c3.x + bi.w);
        float4 row1 = make_float4(c0.y + bi.x, c1.y + bi.y, c2.y + bi.z, c3.y + bi.w);
#pragma unroll
        for (int h2 = 0; h2 < 2; h2++) {
            int r = ty * 8 + 2 * p + h2;
            if (m0 + r < NROW) {
                int m = srow[r];
                int slot = ((m >> 5) << 6) + (m & 31);
                float4 v = h2 ? row1 : row0;
                if (mode == 0) {
                    float* dst = (nb < HH) ? (g_h + (size_t)slot * HH + nb)
                                           : (g_c + (size_t)slot * HH + (nb - HH));
                    *reinterpret_cast<float4*>(dst) = v;
                } else {
                    size_t base = (size_t)slot * G5;
                    float* dst = (nb < G5) ? (g_vl + base + nb) : (g_vr + base + (nb - G5));
                    *reinterpret_cast<float4*>(dst) = v;
                }
            }
        }
    }
}

// ---------------- step GEMM half-tile: 64x64, BK=16, 256 threads, M-packed f32x2 ----
// Thread computes 4 rows (2 packed pairs) x 4 cols. Halves independent (named barriers).
#define STA(buf,k,r) Af[((buf)*16 + (k))*68 + (r)]
#define STB(buf,k,r) Bf[((buf)*16 + (k))*68 + (r)]
__device__ void gemm_step(int step, int nact, int m0, int n0, int t, int half,
    char* hs, const float* __restrict__ Wc)
{
    float* Af = (float*)hs;
    float* Bf = (float*)(hs + STB_OFF);

    const int lrow = t >> 2;        // 0..63
    const int kq   = (t & 3) * 4;

    const float* aptr;
    {
        int m = m0 + lrow;
        int b = (m < nact) ? g_active[m] : g_active[0];
        aptr = g_h + (size_t)(b * NS + 32 + step) * HH + kq;
    }
    const float* bptr;
    {
        int n = n0 + lrow;
        bptr = (n < G5) ? Wc + (size_t)n * 1024 + kq
                        : Wc + (size_t)(n - G5) * 1024 + 512 + kq;
    }

    const int ty = t >> 4;   // rows ty*4
    const int tx = t & 15;   // cols tx*4

    ull acc[2][4];   // [row-pair][col]
#pragma unroll
    for (int i = 0; i < 2; i++)
#pragma unroll
        for (int j = 0; j < 4; j++) acc[i][j] = 0ull;

    float4 ra = *reinterpret_cast<const float4*>(aptr);
    float4 rb = *reinterpret_cast<const float4*>(bptr);
    STA(0, kq + 0, lrow) = ra.x; STA(0, kq + 1, lrow) = ra.y;
    STA(0, kq + 2, lrow) = ra.z; STA(0, kq + 3, lrow) = ra.w;
    STB(0, kq + 0, lrow) = rb.x; STB(0, kq + 1, lrow) = rb.y;
    STB(0, kq + 2, lrow) = rb.z; STB(0, kq + 3, lrow) = rb.w;
    HBAR(half);

    int buf = 0;
    for (int k0 = 16; k0 <= 512; k0 += 16) {
        const bool more = (k0 < 512);
        if (more) {
            ra = *reinterpret_cast<const float4*>(aptr + k0);
            rb = *reinterpret_cast<const float4*>(bptr + k0);
        }
#pragma unroll
        for (int kk = 0; kk < 16; kk++) {
            ull a[2];
            ulonglong2 t0 = *reinterpret_cast<const ulonglong2*>(&STA(buf, kk, ty * 4));
            a[0] = t0.x; a[1] = t0.y;
            float4 b4 = *reinterpret_cast<const float4*>(&STB(buf, kk, tx * 4));
            ull bd[4];
            bd[0] = dup2(b4.x); bd[1] = dup2(b4.y); bd[2] = dup2(b4.z); bd[3] = dup2(b4.w);
#pragma unroll
            for (int i = 0; i < 2; i++)
#pragma unroll
                for (int j = 0; j < 4; j++)
                    ffma2(acc[i][j], a[i], bd[j]);
        }
        if (more) {
            STA(buf ^ 1, kq + 0, lrow) = ra.x; STA(buf ^ 1, kq + 1, lrow) = ra.y;
            STA(buf ^ 1, kq + 2, lrow) = ra.z; STA(buf ^ 1, kq + 3, lrow) = ra.w;
            STB(buf ^ 1, kq + 0, lrow) = rb.x; STB(buf ^ 1, kq + 1, lrow) = rb.y;
            STB(buf ^ 1, kq + 2, lrow) = rb.z; STB(buf ^ 1, kq + 3, lrow) = rb.w;
        }
        HBAR(half);
        buf ^= 1;
    }

    const int nb = n0 + tx * 4;
#pragma unroll
    for (int p = 0; p < 2; p++) {
        float2 c0 = unpk(acc[p][0]), c1 = unpk(acc[p][1]);
        float2 c2 = unpk(acc[p][2]), c3 = unpk(acc[p][3]);
        float4 row0 = make_float4(c0.x, c1.x, c2.x, c3.x);
        float4 row1 = make_float4(c0.y, c1.y, c2.y, c3.y);
#pragma unroll
        for (int h2 = 0; h2 < 2; h2++) {
            int m = m0 + ty * 4 + 2 * p + h2;
            if (m < nact) {
                int b = g_active[m];
                size_t base = (size_t)(b * NS + 32 + step) * G5;
                float* dst = (nb < G5) ? (g_vl + base + nb) : (g_vr + base + (nb - G5));
                *reinterpret_cast<float4*>(dst) = h2 ? row1 : row0;
            }
        }
    }
    HBAR(half);   // protect smem reuse across consecutive tiles in this half
}

// ---------------- pair gates + partial logit (t in 0..127) ----------------
__device__ __forceinline__ float pair_body(int b, int key, int Ls, int Rs, int t,
    const float* __restrict__ b_comp, const float* __restrict__ cq)
{
    const float4* vl  = reinterpret_cast<const float4*>(g_vl + (size_t)(b * NS + Ls) * G5);
    const float4* vr  = reinterpret_cast<const float4*>(g_vr + (size_t)(b * NS + Rs) * G5);
    const float4* bc  = reinterpret_cast<const float4*>(b_comp);
    const float4* cl4 = reinterpret_cast<const float4*>(g_c + (size_t)(b * NS + Ls) * HH);
    const float4* cr4 = reinterpret_cast<const float4*>(g_c + (size_t)(b * NS + Rs) * HH);
    const float4* q4  = reinterpret_cast<const float4*>(cq);

    float vi[4], vfl[4], vfr[4], vu[4], vo[4];
    {
        float* dsts[5] = {vi, vfl, vfr, vu, vo};
#pragma unroll
        for (int g = 0; g < 5; g++) {
            float4 a = vl[g * 128 + t], bb = vr[g * 128 + t], c = bc[g * 128 + t];
            dsts[g][0] = a.x + bb.x + c.x; dsts[g][1] = a.y + bb.y + c.y;
            dsts[g][2] = a.z + bb.z + c.z; dsts[g][3] = a.w + bb.w + c.w;
        }
    }
    float4 cl = cl4[t], cr = cr4[t], qv = q4[t];
    float clv[4] = {cl.x, cl.y, cl.z, cl.w};
    float crv[4] = {cr.x, cr.y, cr.z, cr.w};
    float qa[4]  = {qv.x, qv.y, qv.z, qv.w};
    float hh[4], cc[4], part = 0.f;
#pragma unroll
    for (int e = 0; e < 4; e++) {
        float c = clv[e] * sigf(vfl[e] + 1.f) + crv[e] * sigf(vfr[e] + 1.f)
                + tanhf(vu[e]) * sigf(vi[e]);
        float h = sigf(vo[e]) * tanhf(c);
        cc[e] = c; hh[e] = h;
        part = fmaf(qa[e], h, part);
    }
    reinterpret_cast<float4*>(g_ch + (size_t)(b * NS + key) * HH)[t] = make_float4(hh[0], hh[1], hh[2], hh[3]);
    reinterpret_cast<float4*>(g_cc + (size_t)(b * NS + key) * HH)[t] = make_float4(cc[0], cc[1], cc[2], cc[3]);
    return part;
}

// ---------------- plan for batch b at step i (one warp) ----------------
__device__ __forceinline__ void plan_do(int b, int i, int lane, const int* __restrict__ length)
{
    int ell = length[b];
    if (i + 1 < ell) {
        int npairs = 31 - i;
        int seqv = g_seq[b * 32 + lane];
        bool valid = (lane < ell - i - 1);
        float lg = valid ? g_clog[b * NS + seqv] : -1e9f;
        float mx = lg;
#pragma unroll
        for (int o = 16; o; o >>= 1) mx = fmaxf(mx, __shfl_xor_sync(0xffffffffu, mx, o));
        unsigned bal = __ballot_sync(0xffffffffu, lg == mx);
        int k = __ffs(bal) - 1;   // first-max = jnp.argmax

        int s    = 32 + i;
        int sk   = __shfl_sync(0xffffffffu, seqv, k);
        int skm1 = __shfl_sync(0xffffffffu, seqv, (k > 0) ? (k - 1) : 0);
        int skp2 = __shfl_sync(0xffffffffu, seqv, (k + 2 < 32) ? (k + 2) : 31);

        const float4* sh = reinterpret_cast<const float4*>(g_ch + (size_t)(b * NS + sk) * HH);
        const float4* sc = reinterpret_cast<const float4*>(g_cc + (size_t)(b * NS + sk) * HH);
        float4* dh = reinterpret_cast<float4*>(g_h + (size_t)(b * NS + s) * HH);
        float4* dc = reinterpret_cast<float4*>(g_c + (size_t)(b * NS + s) * HH);
#pragma unroll
        for (int r = 0; r < 4; r++) {
            dh[lane + 32 * r] = sh[lane + 32 * r];
            dc[lane + 32 * r] = sc[lane + 32 * r];
        }
        if (lane == 0) {
            int idx = atomicAdd(&g_nact[i], 1);
            g_active[idx] = b;
            g_jobs[b * 2]     = make_int4(skm1, skm1, s, (k >= 1) ? 1 : 0);
            g_jobs[b * 2 + 1] = make_int4(s, s, skp2, (k <= npairs - 2) ? 1 : 0);
        }
        int nxt = __shfl_down_sync(0xffffffffu, seqv, 1);
        g_seq[b * 32 + lane] = (lane < k) ? seqv : ((lane == k) ? s : nxt);
    } else if (lane == 0) {
        g_jobs[b * 2]     = make_int4(0, 0, 0, 0);
        g_jobs[b * 2 + 1] = make_int4(0, 0, 0, 0);
    }
}

// ---------------- the persistent kernel ----------------
__global__ __launch_bounds__(TPB, 1) void persist_k(
    const float* __restrict__ x, const int* __restrict__ length,
    const float* __restrict__ W_word, const float* __restrict__ b_word,
    const float* __restrict__ W_comp, const float* __restrict__ b_comp,
    const float* __restrict__ cq, float* __restrict__ out)
{
    extern __shared__ __align__(16) char dynp[];
    __shared__ int   srow[128];
    __shared__ float sws[16];

    const int tid  = threadIdx.x;
    const int bid  = blockIdx.x;
    const int half = tid >> 8;     // 0/1
    const int t256 = tid & 255;
    int gen = 0;
    if (tid == 0) gen = g_bar_gen;

    // ---- init: rowmap (block 0), seq (block 1), nact (block 2) ----
    if (bid == 0) {
        int* slen = (int*)dynp;
        if (tid < BB) slen[tid] = length[tid];
        __syncthreads();
        if (tid < BB) {
            int s = 0;
            for (int q = 0; q < tid; q++) s += slen[q];
            int l = slen[tid];
            for (int k = 0; k < l; k++) g_rowmap[s + k] = tid * 32 + k;
            if (tid == BB - 1) g_nrow = s + l;
        }
    }
    if (bid == 1) {
        for (int idx = tid; idx < BB * 32; idx += TPB) g_seq[idx] = idx & 31;
    }
    if (bid == 2 && tid < 32) g_nact[tid] = 0;
    gbar(tid, &gen);

    const int NROW = g_nrow;
    const int MG   = (NROW + 127) >> 7;

    // ---- phase A: word projection over live rows ----
    for (int tt = bid; tt < MG * 8; tt += GRID)
        gemm_big(0, (tt >> 3) * 128, (tt & 7) * 128, NROW, tid, dynp, srow, x, W_word, b_word, W_comp);
    gbar(tid, &gen);

    // ---- phase B: leaf transforms over live rows ----
    for (int tt = bid; tt < MG * 40; tt += GRID)
        gemm_big(1, (tt / 40) * 128, (tt % 40) * 128, NROW, tid, dynp, srow, x, W_word, b_word, W_comp);
    gbar(tid, &gen);

    // ---- phase C: initial candidates (only pairs inside valid prefix) ----
    {
        const int grp = tid >> 7, t2 = tid & 127, w4 = (tid >> 5) & 3;
        for (int p = bid; p < 1984; p += GRID) {
            int j  = p * 4 + grp;
            int b  = j / 31;
            int jj = j - b * 31;
            bool valid = (jj + 1 < length[b]);
            float part = valid ? pair_body(b, jj, jj, jj + 1, t2, b_comp, cq) : 0.f;
#pragma unroll
            for (int o = 16; o; o >>= 1) part += __shfl_xor_sync(0xffffffffu, part, o);
            if ((t2 & 31) == 0) sws[grp * 4 + w4] = part;
            __syncthreads();
            if (t2 == 0 && valid)
                g_clog[b * NS + jj] = (sws[grp*4] + sws[grp*4+1] + sws[grp*4+2] + sws[grp*4+3])
                                      * 0.044194173824159216f;
            __syncthreads();
        }
    }
    gbar(tid, &gen);

    // ---- plan(0): batch b on block b/2 (warp 0 of each half) ----
    {
        int b = bid * 2 + half;
        if (b < BB && t256 < 32) plan_do(b, 0, tid & 31, length);
    }
    gbar(tid, &gen);

    // ---- main loop ----
    for (int i = 0; i < 30; i++) {
        // step GEMM: independent 64x64 half-tiles, spread across SMs first
        {
            int nact  = g_nact[i];
            int ntile = ((nact + 63) >> 6) * 80;
            char* hs = dynp + half * HALF_OFF;
            for (int w = half * GRID + bid; w < ntile; w += 2 * GRID)
                gemm_step(i, nact, (w / 80) * 64, (w % 80) * 64, t256, half, hs, W_comp);
        }
        gbar(tid, &gen);

        // PP: pair jobs of step i + plan(i+1), batch b on block b/2
        {
            int b = bid * 2 + half;
            bool bact = (b < BB);
            const int grp = tid >> 7, t2 = tid & 127, w4 = (tid >> 5) & 3;
            int4 job = make_int4(0, 0, 0, 0);
            if (bact) job = g_jobs[b * 2 + (t256 >> 7)];
            bool jact = bact && job.w;
            float part = jact ? pair_body(b, job.x, job.y, job.z, t2, b_comp, cq) : 0.f;
#pragma unroll
            for (int o = 16; o; o >>= 1) part += __shfl_xor_sync(0xffffffffu, part, o);
            if ((t2 & 31) == 0) sws[grp * 4 + w4] = part;
            __syncthreads();
            if (t2 == 0 && jact)
                g_clog[b * NS + job.x] = (sws[grp*4] + sws[grp*4+1] + sws[grp*4+2] + sws[grp*4+3])
                                         * 0.044194173824159216f;
            __syncthreads();
            if (bact && t256 < 32) plan_do(b, i + 1, tid & 31, length);
        }
        gbar(tid, &gen);
    }

    // ---- output: h of root slot ----
    {
        int b = bid * 2 + half;
        if (b < BB && t256 < 128) {
            int s = g_seq[b * 32];
            const float4* src = reinterpret_cast<const float4*>(g_h + (size_t)(b * NS + s) * HH);
            reinterpret_cast<float4*>(out)[b * 128 + t256] = src[t256];
        }
    }
}

// ---------------- launch ----------------
extern "C" void kernel_launch(void* const* d_in, const int* in_sizes, int n_in,
                              void* d_out, int out_size)
{
    const float* x      = (const float*)d_in[0];
    const int*   length = (const int*)  d_in[1];
    const float* W_word = (const float*)d_in[2];
    const float* b_word = (const float*)d_in[3];
    const float* W_comp = (const float*)d_in[4];
    const float* b_comp = (const float*)d_in[5];
    const float* cq     = (const float*)d_in[6];
    float* out = (float*)d_out;

    cudaFuncSetAttribute(persist_k, cudaFuncAttributeMaxDynamicSharedMemorySize, DYN_BYTES);
    persist_k<<<GRID, TPB, DYN_BYTES>>>(x, length, W_word, b_word, W_comp, b_comp, cq, out);
}

// round 11
// speedup vs baseline: 1.4700x; 1.0372x over previous
#include <cuda_runtime.h>
#include <math.h>

#define BB   256
#define HH   512
#define DD   512
#define NS   64
#define G5   2560
#define GRID 148
#define TPB  512

// dynamic smem:
//  big phase: A float [2][16][132] at 0 (16896 B), B float [2][16][132] at 16896
//  step phase: per half h at h*17408: A [2][16][68] (8704 B), B [2][16][68]
#define DYN_BYTES 36864
#define BIGB_OFF  16896
#define STB_OFF   8704
#define HALF_OFF  17408

typedef unsigned long long ull;

// ---------------- packed fp32 helpers ----------------
__device__ __forceinline__ ull dup2(float a) {
    ull d;
    asm("mov.b64 %0, {%1, %1};" : "=l"(d) : "f"(a));
    return d;
}
__device__ __forceinline__ void ffma2(ull& acc, ull a, ull b) {
    asm("fma.rn.f32x2 %0, %1, %2, %0;" : "+l"(acc) : "l"(a), "l"(b));
}
__device__ __forceinline__ float2 unpk(ull v) {
    float2 r;
    asm("mov.b64 {%0, %1}, %2;" : "=f"(r.x), "=f"(r.y) : "l"(v));
    return r;
}
#define HBAR(h) asm volatile("bar.sync %0, 256;" :: "r"((h) + 1) : "memory")

// ---------------- static device scratch ----------------
__device__ float g_h [BB * NS * HH];
__device__ float g_c [BB * NS * HH];
__device__ float g_ch[BB * NS * HH];
__device__ float g_cc[BB * NS * HH];
__device__ float g_vl[(size_t)BB * NS * G5];
__device__ float g_vr[(size_t)BB * NS * G5];
__device__ float g_pv[BB * 5120];               // split-K partial (ks=1) for new-node transforms
__device__ float g_clog[BB * NS];
__device__ int   g_seq [BB * 32];
__device__ int4  g_jobs[BB * 2];
__device__ int   g_active[BB];
__device__ int   g_nact[32];
__device__ int   g_rowmap[BB * 32];
__device__ int   g_nrow;
__device__ int   g_bar_cnt = 0;
__device__ volatile int g_bar_gen = 0;

__device__ __forceinline__ float sigf(float x) { return 1.f / (1.f + expf(-x)); }

// ---------------- software grid barrier ----------------
__device__ __forceinline__ void gbar(int tid, int* gen)
{
    __syncthreads();
    if (tid == 0) {
        int target = *gen + 1;
        __threadfence();
        if (atomicAdd(&g_bar_cnt, 1) == GRID - 1) {
            g_bar_cnt = 0;
            __threadfence();
            g_bar_gen = target;
        } else {
            while (g_bar_gen - target < 0) __nanosleep(32);
            __threadfence();   // gpu-scope fence: drop stale L1 lines
        }
        *gen = target;
    }
    __syncthreads();
}

// ---------------- big GEMM tile: 128x128, BK=16, 512 threads, M-packed f32x2 ----
#define BIGA(buf,k,r) Af[((buf)*16 + (k))*132 + (r)]
#define BIGB(buf,k,r) Bf[((buf)*16 + (k))*132 + (r)]
__device__ void gemm_big(int mode, int m0, int n0, int NROW, int tid,
    char* dynp, int* __restrict__ srow,
    const float* __restrict__ x, const float* __restrict__ Ww,
    const float* __restrict__ bw, const float* __restrict__ Wc)
{
    float* Af = (float*)dynp;
    float* Bf = (float*)(dynp + BIGB_OFF);

    __syncthreads();
    if (tid < 128) {
        int r = m0 + tid;
        srow[tid] = (r < NROW) ? g_rowmap[r] : g_rowmap[0];
    }
    __syncthreads();

    const int lrow = tid >> 2;        // 0..127
    const int kq   = (tid & 3) * 4;   // 0,4,8,12

    const float* aptr;
    {
        int m = srow[lrow];
        aptr = (mode == 0) ? x + (size_t)m * DD + kq
                           : g_h + (size_t)(((m >> 5) << 6) + (m & 31)) * HH + kq;
    }
    const float* bptr;
    {
        int n = n0 + lrow;
        if (mode == 0) bptr = Ww + (size_t)n * DD + kq;
        else bptr = (n < G5) ? Wc + (size_t)n * 1024 + kq
                             : Wc + (size_t)(n - G5) * 1024 + 512 + kq;
    }

    const int ty = tid >> 5;   // warp id -> rows ty*8 (broadcast)
    const int tx = tid & 31;   // lane -> cols tx*4

    ull acc[4][4];
#pragma unroll
    for (int i = 0; i < 4; i++)
#pragma unroll
        for (int j = 0; j < 4; j++) acc[i][j] = 0ull;

    float4 ra = *reinterpret_cast<const float4*>(aptr);
    float4 rb = *reinterpret_cast<const float4*>(bptr);
    BIGA(0, kq + 0, lrow) = ra.x; BIGA(0, kq + 1, lrow) = ra.y;
    BIGA(0, kq + 2, lrow) = ra.z; BIGA(0, kq + 3, lrow) = ra.w;
    BIGB(0, kq + 0, lrow) = rb.x; BIGB(0, kq + 1, lrow) = rb.y;
    BIGB(0, kq + 2, lrow) = rb.z; BIGB(0, kq + 3, lrow) = rb.w;
    __syncthreads();

    int buf = 0;
    for (int k0 = 16; k0 <= 512; k0 += 16) {
        const bool more = (k0 < 512);
        if (more) {
            ra = *reinterpret_cast<const float4*>(aptr + k0);
            rb = *reinterpret_cast<const float4*>(bptr + k0);
        }
#pragma unroll
        for (int kk = 0; kk < 16; kk++) {
            ull a[4];
            ulonglong2 t0 = *reinterpret_cast<const ulonglong2*>(&BIGA(buf, kk, ty * 8));
            ulonglong2 t1 = *reinterpret_cast<const ulonglong2*>(&BIGA(buf, kk, ty * 8 + 4));
            a[0] = t0.x; a[1] = t0.y; a[2] = t1.x; a[3] = t1.y;
            float4 b4 = *reinterpret_cast<const float4*>(&BIGB(buf, kk, tx * 4));
            ull bd[4];
            bd[0] = dup2(b4.x); bd[1] = dup2(b4.y); bd[2] = dup2(b4.z); bd[3] = dup2(b4.w);
#pragma unroll
            for (int i = 0; i < 4; i++)
#pragma unroll
                for (int j = 0; j < 4; j++)
                    ffma2(acc[i][j], a[i], bd[j]);
        }
        if (more) {
            BIGA(buf ^ 1, kq + 0, lrow) = ra.x; BIGA(buf ^ 1, kq + 1, lrow) = ra.y;
            BIGA(buf ^ 1, kq + 2, lrow) = ra.z; BIGA(buf ^ 1, kq + 3, lrow) = ra.w;
            BIGB(buf ^ 1, kq + 0, lrow) = rb.x; BIGB(buf ^ 1, kq + 1, lrow) = rb.y;
            BIGB(buf ^ 1, kq + 2, lrow) = rb.z; BIGB(buf ^ 1, kq + 3, lrow) = rb.w;
        }
        __syncthreads();
        buf ^= 1;
    }

    const int nb = n0 + tx * 4;
    float4 bi = make_float4(0.f, 0.f, 0.f, 0.f);
    if (mode == 0) bi = *reinterpret_cast<const float4*>(&bw[nb]);
#pragma unroll
    for (int p = 0; p < 4; p++) {
        float2 c0 = unpk(acc[p][0]), c1 = unpk(acc[p][1]);
        float2 c2 = unpk(acc[p][2]), c3 = unpk(acc[p][3]);
        float4 row0 = make_float4(c0.x + bi.x, c1.x + bi.y, c2.x + bi.z, c3.x + bi.w);
        float4 row1 = make_float4(c0.y + bi.x, c1.y + bi.y, c2.y + bi.z, c3.y + bi.w);
#pragma unroll
        for (int h2 = 0; h2 < 2; h2++) {
            int r = ty * 8 + 2 * p + h2;
            if (m0 + r < NROW) {
                int m = srow[r];
                int slot = ((m >> 5) << 6) + (m & 31);
                float4 v = h2 ? row1 : row0;
                if (mode == 0) {
                    float* dst = (nb < HH) ? (g_h + (size_t)slot * HH + nb)
                                           : (g_c + (size_t)slot * HH + (nb - HH));
                    *reinterpret_cast<float4*>(dst) = v;
                } else {
                    size_t base = (size_t)slot * G5;
                    float* dst = (nb < G5) ? (g_vl + base + nb) : (g_vr + base + (nb - G5));
                    *reinterpret_cast<float4*>(dst) = v;
                }
            }
        }
    }
}

// ---------------- step GEMM half-tile: 64x64xK256 (split-K), 256 threads ----
// ks=0 -> write g_vl/g_vr; ks=1 -> write g_pv partial. Halves independent.
#define STA(buf,k,r) Af[((buf)*16 + (k))*68 + (r)]
#define STB(buf,k,r) Bf[((buf)*16 + (k))*68 + (r)]
__device__ void gemm_step(int step, int nact, int m0, int n0, int ks, int t, int half,
    char* hs, const float* __restrict__ Wc)
{
    float* Af = (float*)hs;
    float* Bf = (float*)(hs + STB_OFF);

    const int lrow = t >> 2;        // 0..63
    const int kq   = (t & 3) * 4;
    const int kofs = ks * 256;

    const float* aptr;
    {
        int m = m0 + lrow;
        int b = (m < nact) ? g_active[m] : g_active[0];
        aptr = g_h + (size_t)(b * NS + 32 + step) * HH + kofs + kq;
    }
    const float* bptr;
    {
        int n = n0 + lrow;
        bptr = (n < G5) ? Wc + (size_t)n * 1024 + kofs + kq
                        : Wc + (size_t)(n - G5) * 1024 + 512 + kofs + kq;
    }

    const int ty = t >> 4;   // rows ty*4
    const int tx = t & 15;   // cols tx*4

    ull acc[2][4];
#pragma unroll
    for (int i = 0; i < 2; i++)
#pragma unroll
        for (int j = 0; j < 4; j++) acc[i][j] = 0ull;

    float4 ra = *reinterpret_cast<const float4*>(aptr);
    float4 rb = *reinterpret_cast<const float4*>(bptr);
    STA(0, kq + 0, lrow) = ra.x; STA(0, kq + 1, lrow) = ra.y;
    STA(0, kq + 2, lrow) = ra.z; STA(0, kq + 3, lrow) = ra.w;
    STB(0, kq + 0, lrow) = rb.x; STB(0, kq + 1, lrow) = rb.y;
    STB(0, kq + 2, lrow) = rb.z; STB(0, kq + 3, lrow) = rb.w;
    HBAR(half);

    int buf = 0;
    for (int k0 = 16; k0 <= 256; k0 += 16) {
        const bool more = (k0 < 256);
        if (more) {
            ra = *reinterpret_cast<const float4*>(aptr + k0);
            rb = *reinterpret_cast<const float4*>(bptr + k0);
        }
#pragma unroll
        for (int kk = 0; kk < 16; kk++) {
            ull a[2];
            ulonglong2 t0 = *reinterpret_cast<const ulonglong2*>(&STA(buf, kk, ty * 4));
            a[0] = t0.x; a[1] = t0.y;
            float4 b4 = *reinterpret_cast<const float4*>(&STB(buf, kk, tx * 4));
            ull bd[4];
            bd[0] = dup2(b4.x); bd[1] = dup2(b4.y); bd[2] = dup2(b4.z); bd[3] = dup2(b4.w);
#pragma unroll
            for (int i = 0; i < 2; i++)
#pragma unroll
                for (int j = 0; j < 4; j++)
                    ffma2(acc[i][j], a[i], bd[j]);
        }
        if (more) {
            STA(buf ^ 1, kq + 0, lrow) = ra.x; STA(buf ^ 1, kq + 1, lrow) = ra.y;
            STA(buf ^ 1, kq + 2, lrow) = ra.z; STA(buf ^ 1, kq + 3, lrow) = ra.w;
            STB(buf ^ 1, kq + 0, lrow) = rb.x; STB(buf ^ 1, kq + 1, lrow) = rb.y;
            STB(buf ^ 1, kq + 2, lrow) = rb.z; STB(buf ^ 1, kq + 3, lrow) = rb.w;
        }
        HBAR(half);
        buf ^= 1;
    }

    const int nb = n0 + tx * 4;
#pragma unroll
    for (int p = 0; p < 2; p++) {
        float2 c0 = unpk(acc[p][0]), c1 = unpk(acc[p][1]);
        float2 c2 = unpk(acc[p][2]), c3 = unpk(acc[p][3]);
        float4 row0 = make_float4(c0.x, c1.x, c2.x, c3.x);
        float4 row1 = make_float4(c0.y, c1.y, c2.y, c3.y);
#pragma unroll
        for (int h2 = 0; h2 < 2; h2++) {
            int m = m0 + ty * 4 + 2 * p + h2;
            if (m < nact) {
                int b = g_active[m];
                float4 v = h2 ? row1 : row0;
                if (ks == 0) {
                    size_t base = (size_t)(b * NS + 32 + step) * G5;
                    float* dst = (nb < G5) ? (g_vl + base + nb) : (g_vr + base + (nb - G5));
                    *reinterpret_cast<float4*>(dst) = v;
                } else {
                    *reinterpret_cast<float4*>(g_pv + b * 5120 + nb) = v;
                }
            }
        }
    }
    HBAR(half);   // protect smem reuse across consecutive tiles in this half
}

// ---------------- pair gates + partial logit (t in 0..127) ----------------
__device__ __forceinline__ float pair_body(int b, int key, int Ls, int Rs, int t,
    const float* __restrict__ b_comp, const float* __restrict__ cq)
{
    const float4* vl  = reinterpret_cast<const float4*>(g_vl + (size_t)(b * NS + Ls) * G5);
    const float4* vr  = reinterpret_cast<const float4*>(g_vr + (size_t)(b * NS + Rs) * G5);
    const float4* bc  = reinterpret_cast<const float4*>(b_comp);
    const float4* cl4 = reinterpret_cast<const float4*>(g_c + (size_t)(b * NS + Ls) * HH);
    const float4* cr4 = reinterpret_cast<const float4*>(g_c + (size_t)(b * NS + Rs) * HH);
    const float4* q4  = reinterpret_cast<const float4*>(cq);

    float vi[4], vfl[4], vfr[4], vu[4], vo[4];
    {
        float* dsts[5] = {vi, vfl, vfr, vu, vo};
#pragma unroll
        for (int g = 0; g < 5; g++) {
            float4 a = vl[g * 128 + t], bb = vr[g * 128 + t], c = bc[g * 128 + t];
            dsts[g][0] = a.x + bb.x + c.x; dsts[g][1] = a.y + bb.y + c.y;
            dsts[g][2] = a.z + bb.z + c.z; dsts[g][3] = a.w + bb.w + c.w;
        }
    }
    float4 cl = cl4[t], cr = cr4[t], qv = q4[t];
    float clv[4] = {cl.x, cl.y, cl.z, cl.w};
    float crv[4] = {cr.x, cr.y, cr.z, cr.w};
    float qa[4]  = {qv.x, qv.y, qv.z, qv.w};
    float hh[4], cc[4], part = 0.f;
#pragma unroll
    for (int e = 0; e < 4; e++) {
        float c = clv[e] * sigf(vfl[e] + 1.f) + crv[e] * sigf(vfr[e] + 1.f)
                + tanhf(vu[e]) * sigf(vi[e]);
        float h = sigf(vo[e]) * tanhf(c);
        cc[e] = c; hh[e] = h;
        part = fmaf(qa[e], h, part);
    }
    reinterpret_cast<float4*>(g_ch + (size_t)(b * NS + key) * HH)[t] = make_float4(hh[0], hh[1], hh[2], hh[3]);
    reinterpret_cast<float4*>(g_cc + (size_t)(b * NS + key) * HH)[t] = make_float4(cc[0], cc[1], cc[2], cc[3]);
    return part;
}

// ---------------- plan for batch b at step i (one warp) ----------------
__device__ __forceinline__ void plan_do(int b, int i, int lane, const int* __restrict__ length)
{
    int ell = length[b];
    if (i + 1 < ell) {
        int npairs = 31 - i;
        int seqv = g_seq[b * 32 + lane];
        bool valid = (lane < ell - i - 1);
        float lg = valid ? g_clog[b * NS + seqv] : -1e9f;
        float mx = lg;
#pragma unroll
        for (int o = 16; o; o >>= 1) mx = fmaxf(mx, __shfl_xor_sync(0xffffffffu, mx, o));
        unsigned bal = __ballot_sync(0xffffffffu, lg == mx);
        int k = __ffs(bal) - 1;   // first-max = jnp.argmax

        int s    = 32 + i;
        int sk   = __shfl_sync(0xffffffffu, seqv, k);
        int skm1 = __shfl_sync(0xffffffffu, seqv, (k > 0) ? (k - 1) : 0);
        int skp2 = __shfl_sync(0xffffffffu, seqv, (k + 2 < 32) ? (k + 2) : 31);

        const float4* sh = reinterpret_cast<const float4*>(g_ch + (size_t)(b * NS + sk) * HH);
        const float4* sc = reinterpret_cast<const float4*>(g_cc + (size_t)(b * NS + sk) * HH);
        float4* dh = reinterpret_cast<float4*>(g_h + (size_t)(b * NS + s) * HH);
        float4* dc = reinterpret_cast<float4*>(g_c + (size_t)(b * NS + s) * HH);
#pragma unroll
        for (int r = 0; r < 4; r++) {
            dh[lane + 32 * r] = sh[lane + 32 * r];
            dc[lane + 32 * r] = sc[lane + 32 * r];
        }
        if (lane == 0) {
            int idx = atomicAdd(&g_nact[i], 1);
            g_active[idx] = b;
            g_jobs[b * 2]     = make_int4(skm1, skm1, s, (k >= 1) ? 1 : 0);
            g_jobs[b * 2 + 1] = make_int4(s, s, skp2, (k <= npairs - 2) ? 1 : 0);
        }
        int nxt = __shfl_down_sync(0xffffffffu, seqv, 1);
        g_seq[b * 32 + lane] = (lane < k) ? seqv : ((lane == k) ? s : nxt);
    } else if (lane == 0) {
        g_jobs[b * 2]     = make_int4(0, 0, 0, 0);
        g_jobs[b * 2 + 1] = make_int4(0, 0, 0, 0);
    }
}

// ---------------- the persistent kernel ----------------
__global__ __launch_bounds__(TPB, 1) void persist_k(
    const float* __restrict__ x, const int* __restrict__ length,
    const float* __restrict__ W_word, const float* __restrict__ b_word,
    const float* __restrict__ W_comp, const float* __restrict__ b_comp,
    const float* __restrict__ cq, float* __restrict__ out)
{
    extern __shared__ __align__(16) char dynp[];
    __shared__ int   srow[128];
    __shared__ float sws[16];

    const int tid  = threadIdx.x;
    const int bid  = blockIdx.x;
    const int half = tid >> 8;     // 0/1
    const int t256 = tid & 255;
    int gen = 0;
    if (tid == 0) gen = g_bar_gen;

    // ---- init: rowmap (block 0), seq (block 1), nact (block 2) ----
    if (bid == 0) {
        int* slen = (int*)dynp;
        if (tid < BB) slen[tid] = length[tid];
        __syncthreads();
        if (tid < BB) {
            int s = 0;
            for (int q = 0; q < tid; q++) s += slen[q];
            int l = slen[tid];
            for (int k = 0; k < l; k++) g_rowmap[s + k] = tid * 32 + k;
            if (tid == BB - 1) g_nrow = s + l;
        }
    }
    if (bid == 1) {
        for (int idx = tid; idx < BB * 32; idx += TPB) g_seq[idx] = idx & 31;
    }
    if (bid == 2 && tid < 32) g_nact[tid] = 0;
    gbar(tid, &gen);

    const int NROW = g_nrow;
    const int MG   = (NROW + 127) >> 7;

    // ---- phase A: word projection over live rows ----
    for (int tt = bid; tt < MG * 8; tt += GRID)
        gemm_big(0, (tt >> 3) * 128, (tt & 7) * 128, NROW, tid, dynp, srow, x, W_word, b_word, W_comp);
    gbar(tid, &gen);

    // ---- phase B: leaf transforms over live rows ----
    for (int tt = bid; tt < MG * 40; tt += GRID)
        gemm_big(1, (tt / 40) * 128, (tt % 40) * 128, NROW, tid, dynp, srow, x, W_word, b_word, W_comp);
    gbar(tid, &gen);

    // ---- phase C: initial candidates (only pairs inside valid prefix) ----
    {
        const int grp = tid >> 7, t2 = tid & 127, w4 = (tid >> 5) & 3;
        for (int p = bid; p < 1984; p += GRID) {
            int j  = p * 4 + grp;
            int b  = j / 31;
            int jj = j - b * 31;
            bool valid = (jj + 1 < length[b]);
            float part = valid ? pair_body(b, jj, jj, jj + 1, t2, b_comp, cq) : 0.f;
#pragma unroll
            for (int o = 16; o; o >>= 1) part += __shfl_xor_sync(0xffffffffu, part, o);
            if ((t2 & 31) == 0) sws[grp * 4 + w4] = part;
            __syncthreads();
            if (t2 == 0 && valid)
                g_clog[b * NS + jj] = (sws[grp*4] + sws[grp*4+1] + sws[grp*4+2] + sws[grp*4+3])
                                      * 0.044194173824159216f;
            __syncthreads();
        }
    }
    gbar(tid, &gen);

    // ---- plan(0): batch b on block b/2 (warp 0 of each half) ----
    {
        int b = bid * 2 + half;
        if (b < BB && t256 < 32) plan_do(b, 0, tid & 31, length);
    }
    gbar(tid, &gen);

    // ---- main loop ----
    for (int i = 0; i < 30; i++) {
        // step GEMM: split-K=2, independent 64x64xK256 half-tiles
        {
            int nact   = g_nact[i];
            int ntile2 = (((nact + 63) >> 6) * 80) * 2;
            char* hs = dynp + half * HALF_OFF;
            for (int w = half * GRID + bid; w < ntile2; w += 2 * GRID) {
                int tile = w >> 1, ks = w & 1;
                gemm_step(i, nact, (tile / 80) * 64, (tile % 80) * 64, ks, t256, half, hs, W_comp);
            }
        }
        gbar(tid, &gen);

        // PP: finalize split-K partials, pair jobs of step i, plan(i+1)
        {
            int b = bid * 2 + half;
            bool bact = (b < BB);
            bool bmerged = bact && (i + 1 < length[b]);

            // finalize: g_vl/g_vr[new slot] += g_pv partial (deterministic order)
            if (bmerged) {
                int s = 32 + i;
                const float4* pv = reinterpret_cast<const float4*>(g_pv + b * 5120);
                float4* vl = reinterpret_cast<float4*>(g_vl + (size_t)(b * NS + s) * G5);
                float4* vr = reinterpret_cast<float4*>(g_vr + (size_t)(b * NS + s) * G5);
#pragma unroll
                for (int q = 0; q < 5; q++) {
                    int idx = q * 256 + t256;
                    float4 p = pv[idx];
                    float4* dst = (idx < 640) ? (vl + idx) : (vr + idx - 640);
                    float4 v = *dst;
                    v.x += p.x; v.y += p.y; v.z += p.z; v.w += p.w;
                    *dst = v;
                }
            }
            __syncthreads();

            const int grp = tid >> 7, t2 = tid & 127, w4 = (tid >> 5) & 3;
            int4 job = make_int4(0, 0, 0, 0);
            if (bact) job = g_jobs[b * 2 + (t256 >> 7)];
            bool jact = bact && job.w;
            float part = jact ? pair_body(b, job.x, job.y, job.z, t2, b_comp, cq) : 0.f;
#pragma unroll
            for (int o = 16; o; o >>= 1) part += __shfl_xor_sync(0xffffffffu, part, o);
            if ((t2 & 31) == 0) sws[grp * 4 + w4] = part;
            __syncthreads();
            if (t2 == 0 && jact)
                g_clog[b * NS + job.x] = (sws[grp*4] + sws[grp*4+1] + sws[grp*4+2] + sws[grp*4+3])
                                         * 0.044194173824159216f;
            __syncthreads();
            if (bact && t256 < 32) plan_do(b, i + 1, tid & 31, length);
        }
        gbar(tid, &gen);
    }

    // ---- output: h of root slot ----
    {
        int b = bid * 2 + half;
        if (b < BB && t256 < 128) {
            int s = g_seq[b * 32];
            const float4* src = reinterpret_cast<const float4*>(g_h + (size_t)(b * NS + s) * HH);
            reinterpret_cast<float4*>(out)[b * 128 + t256] = src[t256];
        }
    }
}

// ---------------- launch ----------------
extern "C" void kernel_launch(void* const* d_in, const int* in_sizes, int n_in,
                              void* d_out, int out_size)
{
    const float* x      = (const float*)d_in[0];
    const int*   length = (const int*)  d_in[1];
    const float* W_word = (const float*)d_in[2];
    const float* b_word = (const float*)d_in[3];
    const float* W_comp = (const float*)d_in[4];
    const float* b_comp = (const float*)d_in[5];
    const float* cq     = (const float*)d_in[6];
    float* out = (float*)d_out;

    cudaFuncSetAttribute(persist_k, cudaFuncAttributeMaxDynamicSharedMemorySize, DYN_BYTES);
    persist_k<<<GRID, TPB, DYN_BYTES>>>(x, length, W_word, b_word, W_comp, b_comp, cq, out);
}